// round 1
// baseline (speedup 1.0000x reference)
#include <cuda_runtime.h>

// Problem constants (fixed shapes from the reference):
//   B=4, C_IN=512, H=W=64 -> N=4096, C_QK=256, C_OUT=512
#define NB    4
#define CIN   512
#define NPIX  4096
#define CQK   256
#define COUT  512

// Scratch (device-global arrays; no allocations allowed in kernel_launch)
__device__ float g_Q[(size_t)NB * NPIX * CQK];   //  16.8 MB  [b][n][c]
__device__ float g_K[(size_t)NB * CQK * NPIX];   //  16.8 MB  [b][c][n]
__device__ float g_V[(size_t)NB * NPIX * COUT];  //  33.6 MB  [b][n][o]
__device__ float g_S[(size_t)NB * NPIX * NPIX];  // 268.4 MB  [b][n][m]

// ---------------------------------------------------------------------------
// Generic tiled SGEMM: C[m][n] = scale * sum_k A(m,k)*B(k,n) + bias_row[m] + bias_col[n]
//   A(m,k) at A[m*sam + k*sak], B(k,n) at B[k*sbk + n*sbn]
//   Batched via blockIdx.z with byte-free (element) batch strides.
//   All M,N multiples of 128; K multiple of 8 (true for every call site).
// Tile: 128x128x8, 256 threads, 8x8 micro-tile in 4 quadrants (4x4 each).
// ---------------------------------------------------------------------------
#define BM 128
#define BN 128
#define BK 8

__global__ __launch_bounds__(256) void gemm_kernel(
    const float* __restrict__ A, const float* __restrict__ B, float* __restrict__ C,
    int M, int Nc, int K,
    long sam, long sak, long sbk, long sbn, long ldc,
    long sAb, long sBb, long sCb,
    const float* __restrict__ bias_row, const float* __restrict__ bias_col,
    float scale)
{
    __shared__ float As[BK][BM + 4];
    __shared__ float Bs[BK][BN + 4];

    const int bz = blockIdx.z;
    A += (long)bz * sAb;
    B += (long)bz * sBb;
    C += (long)bz * sCb;

    const int m0 = blockIdx.y * BM;
    const int n0 = blockIdx.x * BN;
    const int tid = threadIdx.x;
    const int tx = tid & 15;   // column group (n)
    const int ty = tid >> 4;   // row group (m)

    float acc[8][8];
#pragma unroll
    for (int i = 0; i < 8; i++)
#pragma unroll
        for (int j = 0; j < 8; j++) acc[i][j] = 0.f;

    for (int kt = 0; kt < K; kt += BK) {
        // ---- load A tile: As[k][m] = A[(m0+m)*sam + (kt+k)*sak]
        if (sak == 1) {
            // k is the contiguous dim -> iterate k fastest
#pragma unroll
            for (int it = 0; it < (BM * BK) / 256; it++) {
                int i = tid + it * 256;
                int k = i & (BK - 1);
                int m = i >> 3;
                As[k][m] = A[(long)(m0 + m) * sam + (long)(kt + k)];
            }
        } else {
            // m is the contiguous dim (sam==1) -> iterate m fastest
#pragma unroll
            for (int it = 0; it < (BM * BK) / 256; it++) {
                int i = tid + it * 256;
                int m = i & (BM - 1);
                int k = i >> 7;
                As[k][m] = A[(long)(m0 + m) + (long)(kt + k) * sak];
            }
        }
        // ---- load B tile: Bs[k][n] = B[(kt+k)*sbk + (n0+n)*sbn]
        if (sbn == 1) {
#pragma unroll
            for (int it = 0; it < (BN * BK) / 256; it++) {
                int i = tid + it * 256;
                int n = i & (BN - 1);
                int k = i >> 7;
                Bs[k][n] = B[(long)(kt + k) * sbk + (long)(n0 + n)];
            }
        } else {
            // k contiguous (sbk==1) -> iterate k fastest
#pragma unroll
            for (int it = 0; it < (BN * BK) / 256; it++) {
                int i = tid + it * 256;
                int k = i & (BK - 1);
                int n = i >> 3;
                Bs[k][n] = B[(long)(kt + k) + (long)(n0 + n) * sbn];
            }
        }
        __syncthreads();

#pragma unroll
        for (int k = 0; k < BK; k++) {
            float a[8], b[8];
#pragma unroll
            for (int i = 0; i < 4; i++) {
                a[i]     = As[k][ty * 4 + i];
                a[4 + i] = As[k][64 + ty * 4 + i];
                b[i]     = Bs[k][tx * 4 + i];
                b[4 + i] = Bs[k][64 + tx * 4 + i];
            }
#pragma unroll
            for (int i = 0; i < 8; i++)
#pragma unroll
                for (int j = 0; j < 8; j++)
                    acc[i][j] += a[i] * b[j];
        }
        __syncthreads();
    }

    // ---- epilogue: scale + biases, coalesced float stores along n
#pragma unroll
    for (int i = 0; i < 8; i++) {
        int mi = (i < 4) ? (ty * 4 + i) : (64 + ty * 4 + (i - 4));
        int m = m0 + mi;
        float br = bias_row ? bias_row[m] : 0.f;
        long base = (long)m * ldc;
#pragma unroll
        for (int j = 0; j < 8; j++) {
            int nj = (j < 4) ? (tx * 4 + j) : (64 + tx * 4 + (j - 4));
            int n = n0 + nj;
            float bc = bias_col ? bias_col[n] : 0.f;
            C[base + n] = acc[i][j] * scale + br + bc;
        }
    }
}

// ---------------------------------------------------------------------------
// Row softmax over rows of length 4096, in place. One block (256 thr) per row.
// ---------------------------------------------------------------------------
__global__ __launch_bounds__(256) void softmax_kernel(float* __restrict__ S)
{
    __shared__ float smax[8];
    __shared__ float ssum[8];

    const long row = blockIdx.x;
    float* p = S + row * (long)NPIX;
    const int tid = threadIdx.x;

    float v[16];
    float mx = -3.4e38f;
#pragma unroll
    for (int i = 0; i < 16; i++) {
        v[i] = p[tid + (i << 8)];
        mx = fmaxf(mx, v[i]);
    }
#pragma unroll
    for (int o = 16; o; o >>= 1) mx = fmaxf(mx, __shfl_xor_sync(0xffffffffu, mx, o));
    if ((tid & 31) == 0) smax[tid >> 5] = mx;
    __syncthreads();
    mx = smax[0];
#pragma unroll
    for (int i = 1; i < 8; i++) mx = fmaxf(mx, smax[i]);

    float s = 0.f;
#pragma unroll
    for (int i = 0; i < 16; i++) {
        v[i] = __expf(v[i] - mx);
        s += v[i];
    }
#pragma unroll
    for (int o = 16; o; o >>= 1) s += __shfl_xor_sync(0xffffffffu, s, o);
    if ((tid & 31) == 0) ssum[tid >> 5] = s;
    __syncthreads();
    s = 0.f;
#pragma unroll
    for (int i = 0; i < 8; i++) s += ssum[i];

    const float inv = 1.f / s;
#pragma unroll
    for (int i = 0; i < 16; i++) p[tid + (i << 8)] = v[i] * inv;
}

// ---------------------------------------------------------------------------
// Launch: 3 projections, S = QK^T * c^-0.5, softmax, out = P V  (direct [b,o,n])
// ---------------------------------------------------------------------------
extern "C" void kernel_launch(void* const* d_in, const int* in_sizes, int n_in,
                              void* d_out, int out_size)
{
    const float* qfeat = (const float*)d_in[0];   // [B, CIN, N]
    const float* kfeat = (const float*)d_in[1];   // [B, CIN, N]
    const float* Wq    = (const float*)d_in[2];   // [CQK, CIN]
    const float* bq    = (const float*)d_in[3];   // [CQK]
    const float* Wk    = (const float*)d_in[4];   // [CQK, CIN]
    const float* bk    = (const float*)d_in[5];   // [CQK]
    const float* Wv    = (const float*)d_in[6];   // [COUT, CIN]
    const float* bv    = (const float*)d_in[7];   // [COUT]
    float* out = (float*)d_out;                   // [B, COUT, N]

    float *Q, *K, *V, *S;
    cudaGetSymbolAddress((void**)&Q, g_Q);
    cudaGetSymbolAddress((void**)&K, g_K);
    cudaGetSymbolAddress((void**)&V, g_V);
    cudaGetSymbolAddress((void**)&S, g_S);

    const dim3 blk(256);
    const float inv_sqrt_c = 0.0625f;  // 256^-0.5

    // Q projection: Q[b][n][o] = sum_c qfeat[b][c][n] * Wq[o][c] + bq[o]
    //   M=N(4096) rows (n), Nc=CQK cols (o), K=CIN
    gemm_kernel<<<dim3(CQK / BN, NPIX / BM, NB), blk>>>(
        qfeat, Wq, Q,
        NPIX, CQK, CIN,
        /*sam*/ 1L, /*sak*/ (long)NPIX, /*sbk*/ 1L, /*sbn*/ (long)CIN, /*ldc*/ (long)CQK,
        (long)CIN * NPIX, 0L, (long)NPIX * CQK,
        nullptr, bq, 1.f);

    // K projection: K[b][o][n] = sum_c Wk[o][c] * kfeat[b][c][n] + bk[o]
    gemm_kernel<<<dim3(NPIX / BN, CQK / BM, NB), blk>>>(
        Wk, kfeat, K,
        CQK, NPIX, CIN,
        /*sam*/ (long)CIN, /*sak*/ 1L, /*sbk*/ (long)NPIX, /*sbn*/ 1L, /*ldc*/ (long)NPIX,
        0L, (long)CIN * NPIX, (long)CQK * NPIX,
        bk, nullptr, 1.f);

    // V projection: V[b][n][o] = sum_c kfeat[b][c][n] * Wv[o][c] + bv[o]
    gemm_kernel<<<dim3(COUT / BN, NPIX / BM, NB), blk>>>(
        kfeat, Wv, V,
        NPIX, COUT, CIN,
        1L, (long)NPIX, 1L, (long)CIN, (long)COUT,
        (long)CIN * NPIX, 0L, (long)NPIX * COUT,
        nullptr, bv, 1.f);

    // S[b][n][m] = (sum_c Q[b][n][c] * K[b][c][m]) * c^-0.5
    gemm_kernel<<<dim3(NPIX / BN, NPIX / BM, NB), blk>>>(
        Q, K, S,
        NPIX, NPIX, CQK,
        (long)CQK, 1L, (long)NPIX, 1L, (long)NPIX,
        (long)NPIX * CQK, (long)CQK * NPIX, (long)NPIX * NPIX,
        nullptr, nullptr, inv_sqrt_c);

    // softmax over last dim, in place
    softmax_kernel<<<NB * NPIX, blk>>>(S);

    // out[b][o][n] = sum_m S[b][n][m] * V[b][m][o]
    //   M=COUT rows (o): A(o,m)=V[m][o]; Nc=N cols (n): B(m,n)=S[n][m]
    gemm_kernel<<<dim3(NPIX / BN, COUT / BM, NB), blk>>>(
        V, S, out,
        COUT, NPIX, NPIX,
        /*sam*/ 1L, /*sak*/ (long)COUT, /*sbk*/ 1L, /*sbn*/ (long)NPIX, /*ldc*/ (long)NPIX,
        (long)NPIX * COUT, (long)NPIX * NPIX, (long)COUT * NPIX,
        nullptr, nullptr, 1.f);
}

// round 2
// speedup vs baseline: 1.4543x; 1.4543x over previous
#include <cuda_runtime.h>
#include <cstdint>

// Problem constants: B=4, C_IN=512, H=W=64 -> N=4096, C_QK=256, C_OUT=512
#define NB    4
#define CIN   512
#define NPIX  4096
#define CQK   256
#define COUT  512

// Scratch
__device__ float g_Q[(size_t)NB * NPIX * CQK];   // [b][n][c]
__device__ float g_K[(size_t)NB * CQK * NPIX];   // [b][c][n]
__device__ float g_V[(size_t)NB * NPIX * COUT];  // [b][n][o]
__device__ float g_S[(size_t)NB * NPIX * NPIX];  // [b][n][m]

// ---------------------------------------------------------------------------
// 3xTF32 tensor-core GEMM:
//   C[m][n] = scale * sum_k A(m,k)*B(k,n) + bias_row[m] + bias_col[n]
//   A(m,k) at A[m*sam + k*sak], B(k,n) at B[k*sbk + n*sbn]; batch via blockIdx.z.
// CTA tile 128x128x16, 256 threads (8 warps = 2m x 4n), warp tile 64x32,
// mma.sync.m16n8k8.tf32, fp32 accumulate, hi/lo split for fp32-level accuracy.
// Requires: M,N % 128 == 0, K % 16 == 0 (true at all call sites).
// ---------------------------------------------------------------------------
#define BM 128
#define BN 128
#define BK 16
#define PAD 8   // smem row pad: bank = (8k+m)%32 -> conflict-free frag loads

__device__ __forceinline__ uint32_t f2tf32(float x) {
    uint32_t r;
    asm("cvt.rna.tf32.f32 %0, %1;" : "=r"(r) : "f"(x));
    return r;
}

__device__ __forceinline__ void split_tf32(float x, uint32_t& hi, uint32_t& lo) {
    hi = f2tf32(x);
    lo = f2tf32(x - __uint_as_float(hi));
}

__device__ __forceinline__ void mma_tf32(float* d, uint32_t a0, uint32_t a1,
                                         uint32_t a2, uint32_t a3,
                                         uint32_t b0, uint32_t b1) {
    asm volatile(
        "mma.sync.aligned.m16n8k8.row.col.f32.tf32.tf32.f32 "
        "{%0,%1,%2,%3}, {%4,%5,%6,%7}, {%8,%9}, {%0,%1,%2,%3};\n"
        : "+f"(d[0]), "+f"(d[1]), "+f"(d[2]), "+f"(d[3])
        : "r"(a0), "r"(a1), "r"(a2), "r"(a3), "r"(b0), "r"(b1));
}

__global__ __launch_bounds__(256) void gemm_tc_kernel(
    const float* __restrict__ A, const float* __restrict__ B, float* __restrict__ C,
    int M, int Nc, int K,
    long sam, long sak, long sbk, long sbn, long ldc,
    long sAb, long sBb, long sCb,
    const float* __restrict__ bias_row, const float* __restrict__ bias_col,
    float scale)
{
    __shared__ float As[BK][BM + PAD];
    __shared__ float Bs[BK][BN + PAD];

    const int bz = blockIdx.z;
    A += (long)bz * sAb;
    B += (long)bz * sBb;
    C += (long)bz * sCb;

    const int m0 = blockIdx.y * BM;
    const int n0 = blockIdx.x * BN;
    const int tid = threadIdx.x;
    const int warp = tid >> 5;
    const int lane = tid & 31;
    const int qr = lane >> 2;   // 0..7
    const int qc = lane & 3;    // 0..3
    const int warp_m = warp & 1;          // 2 warps along m: 64 rows each
    const int warp_n = warp >> 1;         // 4 warps along n: 32 cols each
    const int wm0 = warp_m * 64;
    const int wn0 = warp_n * 32;

    float acc[4][4][4];
#pragma unroll
    for (int i = 0; i < 4; i++)
#pragma unroll
        for (int j = 0; j < 4; j++)
#pragma unroll
            for (int r = 0; r < 4; r++) acc[i][j][r] = 0.f;

    for (int kt = 0; kt < K; kt += BK) {
        // ---- A tile: As[k][m] = A[(m0+m)*sam + (kt+k)*sak]
        if (sak == 1) {
#pragma unroll
            for (int it = 0; it < (BM * BK) / 256; it++) {
                int i = tid + it * 256;
                int k = i & (BK - 1);
                int m = i >> 4;
                As[k][m] = A[(long)(m0 + m) * sam + (long)(kt + k)];
            }
        } else {  // sam == 1
#pragma unroll
            for (int it = 0; it < (BM * BK) / 256; it++) {
                int i = tid + it * 256;
                int m = i & (BM - 1);
                int k = i >> 7;
                As[k][m] = A[(long)(m0 + m) + (long)(kt + k) * sak];
            }
        }
        // ---- B tile: Bs[k][n] = B[(kt+k)*sbk + (n0+n)*sbn]
        if (sbn == 1) {
#pragma unroll
            for (int it = 0; it < (BN * BK) / 256; it++) {
                int i = tid + it * 256;
                int n = i & (BN - 1);
                int k = i >> 7;
                Bs[k][n] = B[(long)(kt + k) * sbk + (long)(n0 + n)];
            }
        } else {  // sbk == 1
#pragma unroll
            for (int it = 0; it < (BN * BK) / 256; it++) {
                int i = tid + it * 256;
                int k = i & (BK - 1);
                int n = i >> 4;
                Bs[k][n] = B[(long)(kt + k) + (long)(n0 + n) * sbn];
            }
        }
        __syncthreads();

#pragma unroll
        for (int ks = 0; ks < BK; ks += 8) {
            // B fragments (hi/lo) for all 4 n-tiles
            uint32_t bh[4][2], bl[4][2];
#pragma unroll
            for (int jn = 0; jn < 4; jn++) {
                int nb = wn0 + jn * 8 + qr;
                split_tf32(Bs[ks + qc][nb],     bh[jn][0], bl[jn][0]);
                split_tf32(Bs[ks + qc + 4][nb], bh[jn][1], bl[jn][1]);
            }
#pragma unroll
            for (int im = 0; im < 4; im++) {
                int mb = wm0 + im * 16;
                uint32_t ah[4], al[4];
                split_tf32(As[ks + qc][mb + qr],         ah[0], al[0]);
                split_tf32(As[ks + qc][mb + qr + 8],     ah[1], al[1]);
                split_tf32(As[ks + qc + 4][mb + qr],     ah[2], al[2]);
                split_tf32(As[ks + qc + 4][mb + qr + 8], ah[3], al[3]);
#pragma unroll
                for (int jn = 0; jn < 4; jn++) {
                    float* d = acc[im][jn];
                    // hi*lo + lo*hi first (small terms), then hi*hi
                    mma_tf32(d, ah[0], ah[1], ah[2], ah[3], bl[jn][0], bl[jn][1]);
                    mma_tf32(d, al[0], al[1], al[2], al[3], bh[jn][0], bh[jn][1]);
                    mma_tf32(d, ah[0], ah[1], ah[2], ah[3], bh[jn][0], bh[jn][1]);
                }
            }
        }
        __syncthreads();
    }

    // ---- epilogue: scale + biases; float2 stores along n
#pragma unroll
    for (int im = 0; im < 4; im++) {
#pragma unroll
        for (int rr = 0; rr < 2; rr++) {
            int m = m0 + wm0 + im * 16 + qr + rr * 8;
            float br = bias_row ? bias_row[m] : 0.f;
            long base = (long)m * ldc;
#pragma unroll
            for (int jn = 0; jn < 4; jn++) {
                int n = n0 + wn0 + jn * 8 + qc * 2;
                float bc0 = bias_col ? bias_col[n] : 0.f;
                float bc1 = bias_col ? bias_col[n + 1] : 0.f;
                float2 v;
                v.x = acc[im][jn][rr * 2 + 0] * scale + br + bc0;
                v.y = acc[im][jn][rr * 2 + 1] * scale + br + bc1;
                *reinterpret_cast<float2*>(&C[base + n]) = v;
            }
        }
    }
}

// ---------------------------------------------------------------------------
// Row softmax over rows of length 4096, in place. One block (256 thr) per row.
// ---------------------------------------------------------------------------
__global__ __launch_bounds__(256) void softmax_kernel(float* __restrict__ S)
{
    __shared__ float smax[8];
    __shared__ float ssum[8];

    const long row = blockIdx.x;
    float* p = S + row * (long)NPIX;
    const int tid = threadIdx.x;

    float v[16];
    float mx = -3.4e38f;
#pragma unroll
    for (int i = 0; i < 16; i++) {
        v[i] = p[tid + (i << 8)];
        mx = fmaxf(mx, v[i]);
    }
#pragma unroll
    for (int o = 16; o; o >>= 1) mx = fmaxf(mx, __shfl_xor_sync(0xffffffffu, mx, o));
    if ((tid & 31) == 0) smax[tid >> 5] = mx;
    __syncthreads();
    mx = smax[0];
#pragma unroll
    for (int i = 1; i < 8; i++) mx = fmaxf(mx, smax[i]);

    float s = 0.f;
#pragma unroll
    for (int i = 0; i < 16; i++) {
        v[i] = __expf(v[i] - mx);
        s += v[i];
    }
#pragma unroll
    for (int o = 16; o; o >>= 1) s += __shfl_xor_sync(0xffffffffu, s, o);
    if ((tid & 31) == 0) ssum[tid >> 5] = s;
    __syncthreads();
    s = 0.f;
#pragma unroll
    for (int i = 0; i < 8; i++) s += ssum[i];

    const float inv = 1.f / s;
#pragma unroll
    for (int i = 0; i < 16; i++) p[tid + (i << 8)] = v[i] * inv;
}

// ---------------------------------------------------------------------------
// Launch
// ---------------------------------------------------------------------------
extern "C" void kernel_launch(void* const* d_in, const int* in_sizes, int n_in,
                              void* d_out, int out_size)
{
    const float* qfeat = (const float*)d_in[0];   // [B, CIN, N]
    const float* kfeat = (const float*)d_in[1];   // [B, CIN, N]
    const float* Wq    = (const float*)d_in[2];   // [CQK, CIN]
    const float* bq    = (const float*)d_in[3];
    const float* Wk    = (const float*)d_in[4];
    const float* bk    = (const float*)d_in[5];
    const float* Wv    = (const float*)d_in[6];   // [COUT, CIN]
    const float* bv    = (const float*)d_in[7];
    float* out = (float*)d_out;                   // [B, COUT, N]

    float *Q, *K, *V, *S;
    cudaGetSymbolAddress((void**)&Q, g_Q);
    cudaGetSymbolAddress((void**)&K, g_K);
    cudaGetSymbolAddress((void**)&V, g_V);
    cudaGetSymbolAddress((void**)&S, g_S);

    const dim3 blk(256);
    const float inv_sqrt_c = 0.0625f;  // 256^-0.5

    // Q[b][n][o] = sum_c qfeat[b][c][n] * Wq[o][c] + bq[o]
    gemm_tc_kernel<<<dim3(CQK / BN, NPIX / BM, NB), blk>>>(
        qfeat, Wq, Q,
        NPIX, CQK, CIN,
        1L, (long)NPIX, 1L, (long)CIN, (long)CQK,
        (long)CIN * NPIX, 0L, (long)NPIX * CQK,
        nullptr, bq, 1.f);

    // K[b][o][n] = sum_c Wk[o][c] * kfeat[b][c][n] + bk[o]
    gemm_tc_kernel<<<dim3(NPIX / BN, CQK / BM, NB), blk>>>(
        Wk, kfeat, K,
        CQK, NPIX, CIN,
        (long)CIN, 1L, (long)NPIX, 1L, (long)NPIX,
        0L, (long)CIN * NPIX, (long)CQK * NPIX,
        bk, nullptr, 1.f);

    // V[b][n][o] = sum_c kfeat[b][c][n] * Wv[o][c] + bv[o]
    gemm_tc_kernel<<<dim3(COUT / BN, NPIX / BM, NB), blk>>>(
        kfeat, Wv, V,
        NPIX, COUT, CIN,
        1L, (long)NPIX, 1L, (long)CIN, (long)COUT,
        (long)CIN * NPIX, 0L, (long)NPIX * COUT,
        nullptr, bv, 1.f);

    // S[b][n][m] = (sum_c Q[b][n][c] * K[b][c][m]) * c^-0.5
    gemm_tc_kernel<<<dim3(NPIX / BN, NPIX / BM, NB), blk>>>(
        Q, K, S,
        NPIX, NPIX, CQK,
        (long)CQK, 1L, (long)NPIX, 1L, (long)NPIX,
        (long)NPIX * CQK, (long)CQK * NPIX, (long)NPIX * NPIX,
        nullptr, nullptr, inv_sqrt_c);

    softmax_kernel<<<NB * NPIX, blk>>>(S);

    // out[b][o][n] = sum_m S[b][n][m] * V[b][m][o]
    gemm_tc_kernel<<<dim3(NPIX / BN, COUT / BM, NB), blk>>>(
        V, S, out,
        COUT, NPIX, NPIX,
        1L, (long)COUT, 1L, (long)NPIX, (long)NPIX,
        (long)NPIX * COUT, (long)NPIX * NPIX, (long)COUT * NPIX,
        nullptr, nullptr, 1.f);
}